// round 10
// baseline (speedup 1.0000x reference)
#include <cuda_runtime.h>
#include <cuda_fp16.h>
#include <mma.h>
#include <cstdint>

using namespace nvcuda;

// Problem constants (fixed: B=8,S=2048,D=1024,E=8,F=4096)
#define T_TOK 16384
#define DIM   1024
#define NE    8
#define FF    4096

typedef __half fp16;

// ---------------- scratch (device globals: allocation-free rule) ----------
__device__ int  g_off[NE + 1];
__device__ int  g_perm[T_TOK];
__device__ int  g_expidx[T_TOK];
__device__ fp16 g_xh[(size_t)T_TOK * DIM];        // x in fp16
__device__ fp16 g_w1h[(size_t)NE * DIM * FF];     // w1 in fp16
__device__ fp16 g_w2h[(size_t)NE * DIM * FF];     // w2 in fp16
__device__ fp16 g_Hh[(size_t)T_TOK * FF];         // hidden in fp16

// ---------------- helpers ---------------------------------------------------
__device__ __forceinline__ void cpasync16(uint32_t dst, const void* src) {
    asm volatile("cp.async.cg.shared.global [%0], [%1], 16;\n"
                 :: "r"(dst), "l"(src));
}
__device__ __forceinline__ void cpasync_commit() {
    asm volatile("cp.async.commit_group;\n" ::: "memory");
}
template <int N>
__device__ __forceinline__ void cpasync_wait() {
    asm volatile("cp.async.wait_group %0;\n" :: "n"(N) : "memory");
}
__device__ __forceinline__ uint32_t smem_u32(const void* p) {
    uint32_t a;
    asm("{ .reg .u64 t; cvta.to.shared.u64 t, %1; cvt.u32.u64 %0, t; }"
        : "=r"(a) : "l"(p));
    return a;
}

// ---------------- small kernels -------------------------------------------
// One warp per token: logits = x_t @ router_w + router_b, argmax (first max).
__global__ void router_kernel(const float* __restrict__ x,
                              const float* __restrict__ rw,
                              const float* __restrict__ rb) {
    int warp = (blockIdx.x * blockDim.x + threadIdx.x) >> 5;
    int lane = threadIdx.x & 31;
    if (warp >= T_TOK) return;
    const float* xr = x + (size_t)warp * DIM;
    float acc[NE];
#pragma unroll
    for (int e = 0; e < NE; e++) acc[e] = 0.f;
    for (int d = lane; d < DIM; d += 32) {
        float xv = xr[d];
        const float4* w4 = (const float4*)(rw + d * NE);
        float4 a = w4[0], b = w4[1];
        acc[0] += xv * a.x; acc[1] += xv * a.y; acc[2] += xv * a.z; acc[3] += xv * a.w;
        acc[4] += xv * b.x; acc[5] += xv * b.y; acc[6] += xv * b.z; acc[7] += xv * b.w;
    }
#pragma unroll
    for (int o = 16; o > 0; o >>= 1)
#pragma unroll
        for (int e = 0; e < NE; e++) acc[e] += __shfl_down_sync(0xffffffffu, acc[e], o);
    if (lane == 0) {
        int bi = 0;
        float bv = acc[0] + rb[0];
#pragma unroll
        for (int e = 1; e < NE; e++) {
            float v = acc[e] + rb[e];
            if (v > bv) { bv = v; bi = e; }   // strict > == first max (jnp.argmax)
        }
        g_expidx[warp] = bi;
    }
}

// Single block: count experts, offsets, lb_loss, then scatter to g_perm.
__global__ void setup_scatter_kernel(float* out_loss, int write_loss) {
    __shared__ int sc[NE];
    __shared__ int scur[NE];
    const int tid = threadIdx.x;   // 256
    if (tid < NE) sc[tid] = 0;
    __syncthreads();
    int cnt[NE];
#pragma unroll
    for (int e = 0; e < NE; e++) cnt[e] = 0;
    for (int t = tid; t < T_TOK; t += 256) {
        int ei = g_expidx[t];
#pragma unroll
        for (int e = 0; e < NE; e++) cnt[e] += (ei == e);
    }
#pragma unroll
    for (int e = 0; e < NE; e++)
        if (cnt[e]) atomicAdd(&sc[e], cnt[e]);
    __syncthreads();
    if (tid == 0) {
        int off = 0;
        for (int e = 0; e < NE; e++) { g_off[e] = off; scur[e] = off; off += sc[e]; }
        g_off[NE] = off;
        if (write_loss) {
            float lb = 0.f;
            for (int e = 0; e < NE; e++) {
                float u = (float)sc[e] / (float)T_TOK - 1.0f / NE;
                lb += u * u;
            }
            *out_loss = lb / NE;
        }
    }
    __syncthreads();
    for (int t = tid; t < T_TOK; t += 256) {
        int e = g_expidx[t];
        int p = atomicAdd(&scur[e], 1);
        g_perm[p] = t;
    }
}

// Fused fp32 -> fp16 conversion: z=0 -> x, z=1 -> w1, z=2 -> w2.
__global__ void convert_kernel(const float4* __restrict__ x,
                               const float4* __restrict__ w1,
                               const float4* __restrict__ w2,
                               uint2* __restrict__ xh,
                               uint2* __restrict__ w1h,
                               uint2* __restrict__ w2h) {
    const int z = blockIdx.z;
    const float4* src = (z == 0) ? x : (z == 1) ? w1 : w2;
    uint2* dh = (z == 0) ? xh : (z == 1) ? w1h : w2h;
    const long n4 = (z == 0) ? (long)T_TOK * DIM / 4 : (long)NE * DIM * FF / 4;
    long i = (long)blockIdx.x * blockDim.x + threadIdx.x;
    const long stride = (long)gridDim.x * blockDim.x;
    for (; i < n4; i += stride) {
        float4 v = src[i];
        __half2 h01 = __floats2half2_rn(v.x, v.y);
        __half2 h23 = __floats2half2_rn(v.z, v.w);
        uint2 hw;
        hw.x = *(uint32_t*)&h01; hw.y = *(uint32_t*)&h23;
        dh[i] = hw;
    }
}

// ---------------- grouped GEMM: pure fp16, fp32 accumulate ------------------
// C = act( A @ W + bias ),  A,W fp16, accum fp32.
// CTA 128x128x64, 128 threads = 4 warps (2M x 2N), warp tile 64x64.
// 2-stage double buffer, prefetch issued right after the stage-free barrier.
// 2 CTAs/SM (71.7 KB smem each) -> decoupled barriers keep HMMA fed.
constexpr int BM = 128, BN = 128, BK = 64;
constexpr int THREADS = 128;
constexpr int ALD = 72;                    // fp16 per A smem row (144 B)
constexpr int BLD = 136;                   // fp16 per B smem row (272 B)
constexpr int A_T = BM * ALD * 2;          // 18432 B
constexpr int B_T = BK * BLD * 2;          // 17408 B
constexpr int STAGE = A_T + B_T;           // 35840 B
constexpr int SMEM_BYTES = 2 * STAGE + 256;   // ~71.9 KB

typedef wmma::fragment<wmma::matrix_a, 16, 16, 16, fp16, wmma::row_major> FragA;
typedef wmma::fragment<wmma::matrix_b, 16, 16, 16, fp16, wmma::row_major> FragB;
typedef wmma::fragment<wmma::accumulator, 16, 16, 16, float> FragC;

template <bool GATHER_A, bool SCATTER_C, bool RELU, bool HALF_OUT>
__global__ __launch_bounds__(THREADS, 2)
void moe_gemm_f1(const fp16* __restrict__ A, const fp16* __restrict__ W,
                 const float* __restrict__ bias, float* __restrict__ C,
                 fp16* __restrict__ Ch, int K, int N) {
    extern __shared__ __align__(16) char smem[];
    const uint32_t base = smem_u32(smem);

    const int tid  = threadIdx.x;
    const int warp = tid >> 5;
    const int lane = tid & 31;
    const int wm = warp >> 1;    // 2 warps over M (64 rows)
    const int wn = warp & 1;     // 2 warps over N (64 cols)

    const int e    = blockIdx.z;
    const int m0   = g_off[e];
    const int rows = g_off[e + 1] - m0;
    const int n0   = blockIdx.x * BN;
    const fp16* We = W + (size_t)e * K * N;
    const float* be = bias + (size_t)e * N;
    const int ktiles = K / BK;

    // cp.async per-thread slots (128 threads)
    // A tile: 128 rows x 128B (64 fp16); thread t stages row t, 8 x 16B chunks.
    // B tile: 64 rows x 256B; thread stages rows (tid>>4)+8q, chunk tid&15.
    const int b_r = tid >> 4;          // 0..7
    const int b_c = tid & 15;          // 16B chunk in BN=128
    const uint32_t aoff = (uint32_t)tid * 144u;

    for (int tm = blockIdx.y; tm * BM < rows; tm += gridDim.y) {
        const int rowt = tm * BM;

        int p = m0 + min(rowt + tid, rows - 1);
        const fp16* aph = A + (GATHER_A ? (size_t)g_perm[p] * K : (size_t)p * K);

        FragC fc[4][4];
#pragma unroll
        for (int i = 0; i < 4; i++)
#pragma unroll
            for (int j = 0; j < 4; j++) wmma::fill_fragment(fc[i][j], 0.f);

        // prefetch k-tile 0 into stage 0
        {
#pragma unroll
            for (int c = 0; c < 8; c++)
                cpasync16(base + aoff + c * 16u, aph + c * 8);
#pragma unroll
            for (int q = 0; q < 8; q++) {
                int r = b_r + 8 * q;
                cpasync16(base + A_T + (uint32_t)r * 272u + b_c * 16u,
                          We + (size_t)r * N + n0 + b_c * 8);
            }
            cpasync_commit();
        }

        for (int kt = 0; kt < ktiles; kt++) {
            cpasync_wait<0>();
            __syncthreads();   // stage kt ready; stage kt^1 free (all warps done)

            if (kt + 1 < ktiles) {
                uint32_t sb = base + ((kt + 1) & 1) * STAGE;
                int kb = (kt + 1) * BK;
#pragma unroll
                for (int c = 0; c < 8; c++)
                    cpasync16(sb + aoff + c * 16u, aph + kb + c * 8);
#pragma unroll
                for (int q = 0; q < 8; q++) {
                    int r = b_r + 8 * q;
                    cpasync16(sb + A_T + (uint32_t)r * 272u + b_c * 16u,
                              We + (size_t)(kb + r) * N + n0 + b_c * 8);
                }
                cpasync_commit();
            }

            const fp16* As = (const fp16*)(smem + (kt & 1) * STAGE);
            const fp16* Bs = (const fp16*)(smem + (kt & 1) * STAGE + A_T);

#pragma unroll
            for (int kk = 0; kk < BK / 16; kk++) {
                FragA fa[4];
#pragma unroll
                for (int i = 0; i < 4; i++)
                    wmma::load_matrix_sync(fa[i],
                        As + (wm * 64 + i * 16) * ALD + kk * 16, ALD);
#pragma unroll
                for (int j = 0; j < 4; j++) {
                    FragB fb;
                    wmma::load_matrix_sync(fb,
                        Bs + kk * 16 * BLD + wn * 64 + j * 16, BLD);
#pragma unroll
                    for (int i = 0; i < 4; i++)
                        wmma::mma_sync(fc[i][j], fa[i], fb, fc[i][j]);
                }
            }
        }

        __syncthreads();   // done with pipeline smem; reuse for staging

        // epilogue: per-warp 16x16 staging (fp32), bias(+relu), store
        float* stage = (float*)(smem) + warp * (16 * 20);
#pragma unroll
        for (int i = 0; i < 4; i++)
#pragma unroll
            for (int j = 0; j < 4; j++) {
                wmma::store_matrix_sync(stage, fc[i][j], 20, wmma::mem_row_major);
                __syncwarp();
#pragma unroll
                for (int t = 0; t < 2; t++) {
                    int idx = lane + 32 * t;        // 64 slots: 16 rows x 4 f4
                    int rr = idx >> 2, cc4 = idx & 3;
                    int r = wm * 64 + i * 16 + rr;
                    int c = n0 + wn * 64 + j * 16 + cc4 * 4;
                    if (rowt + r < rows) {
                        float4 v = *(float4*)&stage[rr * 20 + cc4 * 4];
                        float4 b = *(const float4*)&be[c];
                        v.x += b.x; v.y += b.y; v.z += b.z; v.w += b.w;
                        if (RELU) {
                            v.x = fmaxf(v.x, 0.f); v.y = fmaxf(v.y, 0.f);
                            v.z = fmaxf(v.z, 0.f); v.w = fmaxf(v.w, 0.f);
                        }
                        if (HALF_OUT) {
                            size_t orow = (size_t)(m0 + rowt + r);
                            __half2 p0 = __floats2half2_rn(v.x, v.y);
                            __half2 p1 = __floats2half2_rn(v.z, v.w);
                            uint2 hw;
                            hw.x = *(uint32_t*)&p0; hw.y = *(uint32_t*)&p1;
                            *(uint2*)&Ch[orow * (size_t)N + c] = hw;
                        } else {
                            size_t orow = SCATTER_C ? (size_t)g_perm[m0 + rowt + r]
                                                    : (size_t)(m0 + rowt + r);
                            *(float4*)&C[orow * (size_t)N + c] = v;
                        }
                    }
                }
                __syncwarp();
            }
        __syncthreads();   // staging aliases stage 0; next tm prefetch writes it
    }
}

// ---------------- launch ----------------------------------------------------
extern "C" void kernel_launch(void* const* d_in, const int* in_sizes, int n_in,
                              void* d_out, int out_size) {
    const float* x  = (const float*)d_in[0];
    const float* rw = (const float*)d_in[1];
    const float* rb = (const float*)d_in[2];
    const float* w1 = (const float*)d_in[3];
    const float* b1 = (const float*)d_in[4];
    const float* w2 = (const float*)d_in[5];
    const float* b2 = (const float*)d_in[6];
    float* out = (float*)d_out;

    void* p;
    cudaGetSymbolAddress(&p, g_xh);  fp16* xh  = (fp16*)p;
    cudaGetSymbolAddress(&p, g_w1h); fp16* w1h = (fp16*)p;
    cudaGetSymbolAddress(&p, g_w2h); fp16* w2h = (fp16*)p;
    cudaGetSymbolAddress(&p, g_Hh);  fp16* Hh  = (fp16*)p;

    cudaFuncSetAttribute(moe_gemm_f1<true,  false, true,  true>,
                         cudaFuncAttributeMaxDynamicSharedMemorySize, SMEM_BYTES);
    cudaFuncSetAttribute(moe_gemm_f1<false, true,  false, false>,
                         cudaFuncAttributeMaxDynamicSharedMemorySize, SMEM_BYTES);

    const long long main_elems = (long long)T_TOK * DIM;
    int write_loss = ((long long)out_size > main_elems) ? 1 : 0;

    // 5 launches; ncu captures the 4th -> GEMM1.
    router_kernel<<<T_TOK / 8, 256>>>(x, rw, rb);                          // 1
    setup_scatter_kernel<<<1, 256>>>(out + (size_t)T_TOK * DIM, write_loss); // 2
    convert_kernel<<<dim3(1024, 1, 3), 256>>>(                             // 3
        (const float4*)x, (const float4*)w1, (const float4*)w2,
        (uint2*)xh, (uint2*)w1h, (uint2*)w2h);

    // GEMM1: Hh = fp16(relu(x[perm,:] @ w1[e] + b1[e]))   K=DIM, N=FF
    moe_gemm_f1<true, false, true, true>                                   // 4
        <<<dim3(FF / BN, 16, NE), THREADS, SMEM_BYTES>>>(
            xh, w1h, b1, nullptr, Hh, DIM, FF);
    // GEMM2: out[perm,:] = Hh @ w2[e] + b2[e]             K=FF, N=DIM
    moe_gemm_f1<false, true, false, false>                                 // 5
        <<<dim3(DIM / BN, 16, NE), THREADS, SMEM_BYTES>>>(
            Hh, w2h, b2, out, nullptr, FF, DIM);
}

// round 11
// speedup vs baseline: 1.0605x; 1.0605x over previous
#include <cuda_runtime.h>
#include <cuda_fp16.h>
#include <mma.h>
#include <cstdint>

using namespace nvcuda;

// Problem constants (fixed: B=8,S=2048,D=1024,E=8,F=4096)
#define T_TOK 16384
#define DIM   1024
#define NE    8
#define FF    4096

typedef __half fp16;

// ---------------- scratch (device globals: allocation-free rule) ----------
__device__ int  g_off[NE + 1];
__device__ int  g_perm[T_TOK];
__device__ int  g_expidx[T_TOK];
__device__ fp16 g_xh[(size_t)T_TOK * DIM];        // x in fp16
__device__ fp16 g_w1h[(size_t)NE * DIM * FF];     // w1 in fp16
__device__ fp16 g_w2h[(size_t)NE * DIM * FF];     // w2 in fp16
__device__ fp16 g_Hh[(size_t)T_TOK * FF];         // hidden in fp16

// ---------------- helpers ---------------------------------------------------
__device__ __forceinline__ void cpasync16(uint32_t dst, const void* src) {
    asm volatile("cp.async.cg.shared.global [%0], [%1], 16;\n"
                 :: "r"(dst), "l"(src));
}
__device__ __forceinline__ void cpasync_commit() {
    asm volatile("cp.async.commit_group;\n" ::: "memory");
}
template <int N>
__device__ __forceinline__ void cpasync_wait() {
    asm volatile("cp.async.wait_group %0;\n" :: "n"(N) : "memory");
}
__device__ __forceinline__ uint32_t smem_u32(const void* p) {
    uint32_t a;
    asm("{ .reg .u64 t; cvta.to.shared.u64 t, %1; cvt.u32.u64 %0, t; }"
        : "=r"(a) : "l"(p));
    return a;
}

// ---------------- small kernels -------------------------------------------
// One warp per token: logits = x_t @ router_w + router_b, argmax (first max).
__global__ void router_kernel(const float* __restrict__ x,
                              const float* __restrict__ rw,
                              const float* __restrict__ rb) {
    int warp = (blockIdx.x * blockDim.x + threadIdx.x) >> 5;
    int lane = threadIdx.x & 31;
    if (warp >= T_TOK) return;
    const float* xr = x + (size_t)warp * DIM;
    float acc[NE];
#pragma unroll
    for (int e = 0; e < NE; e++) acc[e] = 0.f;
    for (int d = lane; d < DIM; d += 32) {
        float xv = xr[d];
        const float4* w4 = (const float4*)(rw + d * NE);
        float4 a = w4[0], b = w4[1];
        acc[0] += xv * a.x; acc[1] += xv * a.y; acc[2] += xv * a.z; acc[3] += xv * a.w;
        acc[4] += xv * b.x; acc[5] += xv * b.y; acc[6] += xv * b.z; acc[7] += xv * b.w;
    }
#pragma unroll
    for (int o = 16; o > 0; o >>= 1)
#pragma unroll
        for (int e = 0; e < NE; e++) acc[e] += __shfl_down_sync(0xffffffffu, acc[e], o);
    if (lane == 0) {
        int bi = 0;
        float bv = acc[0] + rb[0];
#pragma unroll
        for (int e = 1; e < NE; e++) {
            float v = acc[e] + rb[e];
            if (v > bv) { bv = v; bi = e; }   // strict > == first max (jnp.argmax)
        }
        g_expidx[warp] = bi;
    }
}

// Single block: count experts, offsets, lb_loss, then scatter to g_perm.
__global__ void setup_scatter_kernel(float* out_loss, int write_loss) {
    __shared__ int sc[NE];
    __shared__ int scur[NE];
    const int tid = threadIdx.x;   // 256
    if (tid < NE) sc[tid] = 0;
    __syncthreads();
    int cnt[NE];
#pragma unroll
    for (int e = 0; e < NE; e++) cnt[e] = 0;
    for (int t = tid; t < T_TOK; t += 256) {
        int ei = g_expidx[t];
#pragma unroll
        for (int e = 0; e < NE; e++) cnt[e] += (ei == e);
    }
#pragma unroll
    for (int e = 0; e < NE; e++)
        if (cnt[e]) atomicAdd(&sc[e], cnt[e]);
    __syncthreads();
    if (tid == 0) {
        int off = 0;
        for (int e = 0; e < NE; e++) { g_off[e] = off; scur[e] = off; off += sc[e]; }
        g_off[NE] = off;
        if (write_loss) {
            float lb = 0.f;
            for (int e = 0; e < NE; e++) {
                float u = (float)sc[e] / (float)T_TOK - 1.0f / NE;
                lb += u * u;
            }
            *out_loss = lb / NE;
        }
    }
    __syncthreads();
    for (int t = tid; t < T_TOK; t += 256) {
        int e = g_expidx[t];
        int p = atomicAdd(&scur[e], 1);
        g_perm[p] = t;
    }
}

// Fused fp32 -> fp16 conversion: z=0 -> x, z=1 -> w1, z=2 -> w2.
__global__ void convert_kernel(const float4* __restrict__ x,
                               const float4* __restrict__ w1,
                               const float4* __restrict__ w2,
                               uint2* __restrict__ xh,
                               uint2* __restrict__ w1h,
                               uint2* __restrict__ w2h) {
    const int z = blockIdx.z;
    const float4* src = (z == 0) ? x : (z == 1) ? w1 : w2;
    uint2* dh = (z == 0) ? xh : (z == 1) ? w1h : w2h;
    const long n4 = (z == 0) ? (long)T_TOK * DIM / 4 : (long)NE * DIM * FF / 4;
    long i = (long)blockIdx.x * blockDim.x + threadIdx.x;
    const long stride = (long)gridDim.x * blockDim.x;
    for (; i < n4; i += stride) {
        float4 v = src[i];
        __half2 h01 = __floats2half2_rn(v.x, v.y);
        __half2 h23 = __floats2half2_rn(v.z, v.w);
        uint2 hw;
        hw.x = *(uint32_t*)&h01; hw.y = *(uint32_t*)&h23;
        dh[i] = hw;
    }
}

// ---------------- grouped GEMM: pure fp16, fp32 accumulate ------------------
// C = act( A @ W + bias ),  A,W fp16, accum fp32.
// CTA 128x256x64, 256 threads = 8 warps (2M x 4N), warp tile 64x64.
// 2-stage double buffer, 16 barriers/GEMM1, 4 kk per barrier.
// A-fragment rotating double-buffer + warp-staggered kk order.
constexpr int BM = 128, BN = 256, BK = 64;
constexpr int THREADS = 256;
constexpr int ALD = 72;                    // fp16 per A smem row (144 B)
constexpr int BLD = 264;                   // fp16 per B smem row (528 B)
constexpr int A_T = BM * ALD * 2;          // 18432 B
constexpr int B_T = BK * BLD * 2;          // 33792 B
constexpr int STAGE = A_T + B_T;           // 52224 B
constexpr int SMEM_BYTES = 2 * STAGE + 256;   // ~102.3 KB

typedef wmma::fragment<wmma::matrix_a, 16, 16, 16, fp16, wmma::row_major> FragA;
typedef wmma::fragment<wmma::matrix_b, 16, 16, 16, fp16, wmma::row_major> FragB;
typedef wmma::fragment<wmma::accumulator, 16, 16, 16, float> FragC;

template <bool GATHER_A, bool SCATTER_C, bool RELU, bool HALF_OUT>
__global__ __launch_bounds__(THREADS, 1)
void moe_gemm_f1(const fp16* __restrict__ A, const fp16* __restrict__ W,
                 const float* __restrict__ bias, float* __restrict__ C,
                 fp16* __restrict__ Ch, int K, int N) {
    extern __shared__ __align__(16) char smem[];
    const uint32_t base = smem_u32(smem);

    const int tid  = threadIdx.x;
    const int warp = tid >> 5;
    const int lane = tid & 31;
    const int wm = warp >> 2;    // 2 warps over M (64 rows)
    const int wn = warp & 3;     // 4 warps over N (64 cols)
    const int kkoff = (warp >> 2) << 1;   // stagger: SMSP-sharing warps offset 2

    const int e    = blockIdx.z;
    const int m0   = g_off[e];
    const int rows = g_off[e + 1] - m0;
    const int n0   = blockIdx.x * BN;
    const fp16* We = W + (size_t)e * K * N;
    const float* be = bias + (size_t)e * N;
    const int ktiles = K / BK;

    // cp.async per-thread slots (256 threads)
    // A tile: 128 rows x 128B; thread: row tid>>1, 4 chunks at ((tid&1)*4+c)*16B
    // B tile: 64 rows x 512B; thread: rows (tid>>5)+8q (q<8), chunk tid&31
    const int a_r = tid >> 1;
    const int a_c = (tid & 1) * 4;     // first 16B chunk index (of 8 per row)
    const int b_r = tid >> 5;          // 0..7
    const int b_c = tid & 31;          // 16B chunk in BN=256
    const uint32_t aoff = (uint32_t)a_r * 144u + (uint32_t)a_c * 16u;

    for (int tm = blockIdx.y; tm * BM < rows; tm += gridDim.y) {
        const int rowt = tm * BM;

        int p = m0 + min(rowt + a_r, rows - 1);
        const fp16* aph = A + (GATHER_A ? (size_t)g_perm[p] * K : (size_t)p * K)
                            + a_c * 8;

        FragC fc[4][4];
#pragma unroll
        for (int i = 0; i < 4; i++)
#pragma unroll
            for (int j = 0; j < 4; j++) wmma::fill_fragment(fc[i][j], 0.f);

        // prefetch k-tile 0 into stage 0
        {
#pragma unroll
            for (int c = 0; c < 4; c++)
                cpasync16(base + aoff + c * 16u, aph + c * 8);
#pragma unroll
            for (int q = 0; q < 8; q++) {
                int r = b_r + 8 * q;
                cpasync16(base + A_T + (uint32_t)r * 528u + b_c * 16u,
                          We + (size_t)r * N + n0 + b_c * 8);
            }
            cpasync_commit();
        }

        for (int kt = 0; kt < ktiles; kt++) {
            cpasync_wait<0>();
            __syncthreads();   // stage kt ready; stage kt^1 free

            if (kt + 1 < ktiles) {
                uint32_t sb = base + ((kt + 1) & 1) * STAGE;
                int kb = (kt + 1) * BK;
#pragma unroll
                for (int c = 0; c < 4; c++)
                    cpasync16(sb + aoff + c * 16u, aph + kb + c * 8);
#pragma unroll
                for (int q = 0; q < 8; q++) {
                    int r = b_r + 8 * q;
                    cpasync16(sb + A_T + (uint32_t)r * 528u + b_c * 16u,
                              We + (size_t)(kb + r) * N + n0 + b_c * 8);
                }
                cpasync_commit();
            }

            const fp16* As = (const fp16*)(smem + (kt & 1) * STAGE);
            const fp16* Bs = (const fp16*)(smem + (kt & 1) * STAGE + A_T);

#pragma unroll
            for (int kkx = 0; kkx < BK / 16; kkx++) {
                const int kk = (kkx + kkoff) & 3;   // warp-staggered order
                FragB fb[4];
#pragma unroll
                for (int j = 0; j < 4; j++)
                    wmma::load_matrix_sync(fb[j],
                        Bs + kk * 16 * BLD + wn * 64 + j * 16, BLD);
                FragA fa[2];
                wmma::load_matrix_sync(fa[0],
                    As + (wm * 64) * ALD + kk * 16, ALD);
#pragma unroll
                for (int i = 0; i < 4; i++) {
                    if (i < 3)
                        wmma::load_matrix_sync(fa[(i + 1) & 1],
                            As + (wm * 64 + (i + 1) * 16) * ALD + kk * 16, ALD);
#pragma unroll
                    for (int j = 0; j < 4; j++)
                        wmma::mma_sync(fc[i][j], fa[i & 1], fb[j], fc[i][j]);
                }
            }
        }

        __syncthreads();   // done with pipeline smem; reuse for staging

        // epilogue: per-warp 16x16 staging (fp32), bias(+relu), store
        float* stage = (float*)(smem) + warp * (16 * 20);
#pragma unroll
        for (int i = 0; i < 4; i++)
#pragma unroll
            for (int j = 0; j < 4; j++) {
                wmma::store_matrix_sync(stage, fc[i][j], 20, wmma::mem_row_major);
                __syncwarp();
#pragma unroll
                for (int t = 0; t < 2; t++) {
                    int idx = lane + 32 * t;        // 64 slots: 16 rows x 4 f4
                    int rr = idx >> 2, cc4 = idx & 3;
                    int r = wm * 64 + i * 16 + rr;
                    int c = n0 + wn * 64 + j * 16 + cc4 * 4;
                    if (rowt + r < rows) {
                        float4 v = *(float4*)&stage[rr * 20 + cc4 * 4];
                        float4 b = *(const float4*)&be[c];
                        v.x += b.x; v.y += b.y; v.z += b.z; v.w += b.w;
                        if (RELU) {
                            v.x = fmaxf(v.x, 0.f); v.y = fmaxf(v.y, 0.f);
                            v.z = fmaxf(v.z, 0.f); v.w = fmaxf(v.w, 0.f);
                        }
                        if (HALF_OUT) {
                            size_t orow = (size_t)(m0 + rowt + r);
                            __half2 p0 = __floats2half2_rn(v.x, v.y);
                            __half2 p1 = __floats2half2_rn(v.z, v.w);
                            uint2 hw;
                            hw.x = *(uint32_t*)&p0; hw.y = *(uint32_t*)&p1;
                            *(uint2*)&Ch[orow * (size_t)N + c] = hw;
                        } else {
                            size_t orow = SCATTER_C ? (size_t)g_perm[m0 + rowt + r]
                                                    : (size_t)(m0 + rowt + r);
                            *(float4*)&C[orow * (size_t)N + c] = v;
                        }
                    }
                }
                __syncwarp();
            }
        __syncthreads();   // staging aliases stage 0; next tm prefetch writes it
    }
}

// ---------------- launch ----------------------------------------------------
extern "C" void kernel_launch(void* const* d_in, const int* in_sizes, int n_in,
                              void* d_out, int out_size) {
    const float* x  = (const float*)d_in[0];
    const float* rw = (const float*)d_in[1];
    const float* rb = (const float*)d_in[2];
    const float* w1 = (const float*)d_in[3];
    const float* b1 = (const float*)d_in[4];
    const float* w2 = (const float*)d_in[5];
    const float* b2 = (const float*)d_in[6];
    float* out = (float*)d_out;

    void* p;
    cudaGetSymbolAddress(&p, g_xh);  fp16* xh  = (fp16*)p;
    cudaGetSymbolAddress(&p, g_w1h); fp16* w1h = (fp16*)p;
    cudaGetSymbolAddress(&p, g_w2h); fp16* w2h = (fp16*)p;
    cudaGetSymbolAddress(&p, g_Hh);  fp16* Hh  = (fp16*)p;

    cudaFuncSetAttribute(moe_gemm_f1<true,  false, true,  true>,
                         cudaFuncAttributeMaxDynamicSharedMemorySize, SMEM_BYTES);
    cudaFuncSetAttribute(moe_gemm_f1<false, true,  false, false>,
                         cudaFuncAttributeMaxDynamicSharedMemorySize, SMEM_BYTES);

    const long long main_elems = (long long)T_TOK * DIM;
    int write_loss = ((long long)out_size > main_elems) ? 1 : 0;

    // 5 launches; ncu captures the 4th -> GEMM1.
    router_kernel<<<T_TOK / 8, 256>>>(x, rw, rb);                          // 1
    setup_scatter_kernel<<<1, 256>>>(out + (size_t)T_TOK * DIM, write_loss); // 2
    convert_kernel<<<dim3(1024, 1, 3), 256>>>(                             // 3
        (const float4*)x, (const float4*)w1, (const float4*)w2,
        (uint2*)xh, (uint2*)w1h, (uint2*)w2h);

    // GEMM1: Hh = fp16(relu(x[perm,:] @ w1[e] + b1[e]))   K=DIM, N=FF
    moe_gemm_f1<true, false, true, true>                                   // 4
        <<<dim3(FF / BN, 16, NE), THREADS, SMEM_BYTES>>>(
            xh, w1h, b1, nullptr, Hh, DIM, FF);
    // GEMM2: out[perm,:] = Hh @ w2[e] + b2[e]             K=FF, N=DIM
    moe_gemm_f1<false, true, false, false>                                 // 5
        <<<dim3(DIM / BN, 16, NE), THREADS, SMEM_BYTES>>>(
            Hh, w2h, b2, out, nullptr, FF, DIM);
}